// round 14
// baseline (speedup 1.0000x reference)
#include <cuda_runtime.h>
#include <math.h>

#define N_BOX 256
#define M_PTS 512
#define KHALF 128                 // k-pairs per block (256 m-points)
#define NBLK  (N_BOX * 2 * 2)     // 1024: boxes x 2 j-halves x 2 k-halves

// c2 = log2(e) / (2 * THETA2^2), THETA2 = 400
#define C2  (1.44269504088896340736f / 320000.0f)
#define L2E 1.44269504088896340736f
#define MAGIC 12582912.0f         // 1.5 * 2^23

__device__ float g_partials[NBLK];
__device__ unsigned int g_count = 0u;   // reset by last block each run

typedef unsigned long long ull;
typedef unsigned int uint32;

__device__ __forceinline__ ull pk(float lo, float hi) {
    ull r; asm("mov.b64 %0, {%1, %2};" : "=l"(r) : "f"(lo), "f"(hi)); return r;
}
__device__ __forceinline__ void upk(float& lo, float& hi, ull v) {
    asm("mov.b64 {%0, %1}, %2;" : "=f"(lo), "=f"(hi) : "l"(v));
}
__device__ __forceinline__ ull fma2(ull a, ull b, ull c) {
    ull d; asm("fma.rn.f32x2 %0, %1, %2, %3;" : "=l"(d) : "l"(a), "l"(b), "l"(c)); return d;
}
__device__ __forceinline__ ull add2(ull a, ull b) {
    ull d; asm("add.rn.f32x2 %0, %1, %2;" : "=l"(d) : "l"(a), "l"(b)); return d;
}
__device__ __forceinline__ ull sub2(ull a, ull b) {
    ull d; asm("sub.rn.f32x2 %0, %1, %2;" : "=l"(d) : "l"(a), "l"(b)); return d;
}
__device__ __forceinline__ float ex2s(float x) {
    float y; asm("ex2.approx.f32 %0, %1;" : "=f"(y) : "f"(x)); return y;
}

struct PrepOut {
    float mx, my, P, u, v;   // k-side
    float Gx, Gy, gx, gy;    // j-side
};

// ---------------------------------------------------------------------------
// Fully fused kernel. Block = (box i, j-half, k-half); 128 threads.
// Core: 2 j's/thread over 128 k-pairs. 3 of 4 k-pairs use hardware ex2
// (MUFU); 1 of 4 uses a packed-f32x2 software exp2 on the FMA/ALU pipes
// (deg-4 poly + magic-round + integer exponent insertion), balancing the
// two pipes (~24-25 cyc/iter each vs 32 MUFU-only).
// ---------------------------------------------------------------------------
__global__ void __launch_bounds__(128, 7) fused_kernel(
    const float* __restrict__ pred,
    const float* __restrict__ target,
    const float* __restrict__ mask,
    const float* __restrict__ grad_x,
    const float* __restrict__ grad_y,
    const float* __restrict__ offset,
    float* __restrict__ out)
{
    __shared__ __align__(16) ull sK[KHALF * 6];  // 48B per k-pair, interleaved
    __shared__ float sWarp[4];
    __shared__ int   sLast;

    const int b   = blockIdx.x;
    const int i   = b >> 2;
    const int jc  = (b >> 1) & 1;
    const int kc  = b & 1;
    const int tid = threadIdx.x;

    // ---- per-box scalars (uniform within block; broadcast loads) ----
    const float off0 = offset[2 * i], off1 = offset[2 * i + 1];
    const float px = pred[5 * i]     - off0;
    const float py = pred[5 * i + 1] - off1;
    const float pw = pred[5 * i + 2];
    const float ph = pred[5 * i + 3];
    const float pa = pred[5 * i + 4];
    const float gxc = target[5 * i]     - off0;
    const float gyc = target[5 * i + 1] - off1;
    const float gw  = target[5 * i + 2];
    const float gh  = target[5 * i + 3];
    const float ga  = target[5 * i + 4];

    float cga, sga;  sincosf(ga, &sga, &cga);
    float cpa, spa;  sincosf(pa, &spa, &cpa);
    const float inv_gw = 1.0f / gw;
    const float inv_gh = 1.0f / gh;

    // ---- inline prep for one m-point ----
    auto prep = [&](int m) -> PrepOut {
        const int idx = i * M_PTS + m;
        const float2 mm = ((const float2*)mask)[idx];
        const float mx = mm.x, my = mm.y;

        const float dx = mx - gxc, dy = my - gyc;
        const float r2  = dx * dx + dy * dy;
        const float rin = rsqrtf(fmaxf(r2, 1e-30f));
        const float d   = r2 * rin;
        float arg = -dx * rin;                       // cos(acosv)
        arg = fminf(1.0f, fmaxf(-1.0f, arg));
        const float st = fabsf(dy) * rin;            // sin(acosv)
        const bool  spos = (gyc >= my);              // beta = ga + s*acosv
        const float s = spos ? 1.0f : -1.0f;

        const float cb = cga * arg - s * (sga * st); // cos(beta)
        const float sb = sga * arg + s * (cga * st); // sin(beta)

        const float d_w = fabsf(d * cb);
        const float d_h = fabsf(d * sb);

        const float e1 = ex2s(L2E * 15.0f * (d_w - gw) * inv_gw);
        const float e2 = ex2s(L2E * 15.0f * (d_h - gh) * inv_gh);
        const float a1 = 1.0f / ((1.0f + e1) * (1.0f + e2));

        const float dwp = pw * d_w * inv_gw;
        const float dhp = ph * d_h * inv_gh;
        const float wx =  dwp * cpa, wy = dwp * spa;
        const float hx = -dhp * spa, hy = dhp * cpa;

        bool q2, q3, q4;
        if (spos) {
            q2 = (ga <= 0.0f) && (arg >= cga);
            q3 = false;
            q4 = (arg < sga) && ((ga <= 0.0f) || (arg >= -cga));
        } else {
            q2 = (arg > -sga) && ((ga <= 0.0f) || (arg <= cga));
            q3 = (arg <= -sga) && ((ga >= 0.0f) || (arg > -cga));
            q4 = false;
        }

        float gpx, gpy;
        if (q2)      { gpx =  wx - hx;  gpy =  wy - hy; }
        else if (q3) { gpx =  wx + hx;  gpy =  wy + hy; }
        else if (q4) { gpx = -wx + hx;  gpy = -wy + hy; }
        else         { gpx = -wx - hx;  gpy = -wy - hy; }

        const float gxv = grad_x[idx];
        const float gyv = grad_y[idx];

        PrepOut o;
        o.mx = mx; o.my = my;
        o.P  = C2 * (mx * mx + my * my);
        o.u  = a1 * gxv;
        o.v  = a1 * gyv;
        o.Gx = px + gpx; o.Gy = py + gpy;
        o.gx = gxv; o.gy = gyv;
        return o;
    };

    // ---- phase 1a: k-side (pair slot tid, m = kc*256 + 2tid, +1) ----
    {
        const int m0 = kc * 256 + 2 * tid;
        const PrepOut k0 = prep(m0);
        const PrepOut k1 = prep(m0 + 1);
        ull* dst = &sK[tid * 6];
        ((float4*)dst)[0] = make_float4(k0.mx, k1.mx, k0.my, k1.my);
        ((float4*)dst)[1] = make_float4(k0.P,  k1.P,  k0.u,  k1.u);
        ((float2*)dst)[4] = make_float2(k0.v,  k1.v);
    }

    // ---- phase 1b: j-side (own j's: jc*256 + tid, +128) ----
    const PrepOut J0 = prep(jc * 256 + tid);
    const PrepOut J1 = prep(jc * 256 + tid + 128);
    __syncthreads();

    const float na0 = -2.0f * C2 * J0.Gx;
    const float nb0 = -2.0f * C2 * J0.Gy;
    const float na1 = -2.0f * C2 * J1.Gx;
    const float nb1 = -2.0f * C2 * J1.Gy;
    const float twoQ0 = ex2s(C2 * (J0.Gx * J0.Gx + J0.Gy * J0.Gy));
    const float twoQ1 = ex2s(C2 * (J1.Gx * J1.Gx + J1.Gy * J1.Gy));

    // packed constants (warp-uniform; expect UR allocation)
    const ull magic2 = pk(MAGIC, MAGIC);
    const ull c4p = pk(9.61812911e-3f, 9.61812911e-3f);
    const ull c3p = pk(5.55041087e-2f, 5.55041087e-2f);
    const ull c2p = pk(2.40226507e-1f, 2.40226507e-1f);
    const ull c1p = pk(6.93147181e-1f, 6.93147181e-1f);
    const ull one2 = pk(1.0f, 1.0f);

    // packed software exp2: magic round + deg-4 Horner + exponent insert
    auto exp2sw = [&](float tl, float th) -> ull {
        const ull t  = pk(tl, th);
        const ull r  = add2(t, magic2);     // bits: 0x4B400000 + round(t)
        const ull fn = sub2(r, magic2);
        const ull fr = sub2(t, fn);         // f in [-0.5, 0.5]
        ull p = fma2(fr, c4p, c3p);
        p = fma2(p, fr, c2p);
        p = fma2(p, fr, c1p);
        p = fma2(p, fr, one2);
        const uint32 rlo = (uint32)r, rhi = (uint32)(r >> 32);
        const uint32 elo = (uint32)p + (rlo << 23);          // exact exp add
        const uint32 ehi = (uint32)(p >> 32) + (rhi << 23);
        return ((ull)ehi << 32) | (ull)elo;
    };

    // ---- phase 2: core loop, 3 hw-pairs : 1 sw-pair per group of 4 ----
    ull A0 = 0, B0 = 0, A1 = 0, B1 = 0;
    const float* f = (const float*)sK;

    auto body = [&](const float* q, bool sw) {
        const float4 xy = *(const float4*)(q);      // mx0,mx1,my0,my1
        const float4 pu = *(const float4*)(q + 4);  // P0,P1,u0,u1
        const float2 vv = *(const float2*)(q + 8);  // v0,v1
        const ull u2 = pk(pu.z, pu.w);
        const ull v2 = pk(vv.x, vv.y);

        float t0l = fmaf(na0, xy.x, pu.x);
        t0l = fmaf(nb0, xy.z, t0l);
        float t0h = fmaf(na0, xy.y, pu.y);
        t0h = fmaf(nb0, xy.w, t0h);
        const ull e0 = sw ? exp2sw(t0l, t0h) : pk(ex2s(t0l), ex2s(t0h));
        A0 = fma2(e0, u2, A0);
        B0 = fma2(e0, v2, B0);

        float t1l = fmaf(na1, xy.x, pu.x);
        t1l = fmaf(nb1, xy.z, t1l);
        float t1h = fmaf(na1, xy.y, pu.y);
        t1h = fmaf(nb1, xy.w, t1h);
        const ull e1 = sw ? exp2sw(t1l, t1h) : pk(ex2s(t1l), ex2s(t1h));
        A1 = fma2(e1, u2, A1);
        B1 = fma2(e1, v2, B1);
    };

#pragma unroll 2
    for (int kg = 0; kg < KHALF; kg += 4, f += 48) {
        body(f,      false);
        body(f + 12, false);
        body(f + 24, false);
        body(f + 36, true);     // software exp2 on FMA/ALU pipes
    }

    float al, ah, bl, bh;
    upk(al, ah, A0); upk(bl, bh, B0);
    float partial = (J0.gx * (al + ah) + J0.gy * (bl + bh)) * twoQ0;
    upk(al, ah, A1); upk(bl, bh, B1);
    partial += (J1.gx * (al + ah) + J1.gy * (bl + bh)) * twoQ1;

    // ---- phase 3: deterministic block reduction (4 warps) ----
#pragma unroll
    for (int o = 16; o > 0; o >>= 1)
        partial += __shfl_down_sync(0xffffffffu, partial, o);
    if ((tid & 31) == 0) sWarp[tid >> 5] = partial;
    __syncthreads();

    if (tid == 0) {
        g_partials[b] = sWarp[0] + sWarp[1] + sWarp[2] + sWarp[3];
        __threadfence();
        unsigned int old = atomicAdd(&g_count, 1u);
        sLast = (old == NBLK - 1) ? 1 : 0;
    }
    __syncthreads();

    // last block: fixed-order final reduction, then reset counter
    if (sLast) {
        float s = 0.0f;
#pragma unroll
        for (int r = 0; r < NBLK / 128; ++r)
            s += __ldcg(&g_partials[tid + r * 128]);
#pragma unroll
        for (int o = 16; o > 0; o >>= 1)
            s += __shfl_down_sync(0xffffffffu, s, o);
        if ((tid & 31) == 0) sWarp[tid >> 5] = s;
        __syncthreads();
        if (tid == 0) {
            float v = sWarp[0] + sWarp[1] + sWarp[2] + sWarp[3];
            const double scale = 1.0 / ((double)N_BOX * (double)M_PTS * (double)M_PTS *
                                        2.0 * 3.14159265358979323846 * 400.0);
            *out = (float)((double)v * scale);
            g_count = 0u;   // ready for next graph replay
        }
    }
}

// ---------------------------------------------------------------------------
extern "C" void kernel_launch(void* const* d_in, const int* in_sizes, int n_in,
                              void* d_out, int out_size)
{
    const float* pred    = (const float*)d_in[0];
    const float* target  = (const float*)d_in[1];
    const float* mask    = (const float*)d_in[2];
    const float* grad_x  = (const float*)d_in[3];
    const float* grad_y  = (const float*)d_in[4];
    const float* offset  = (const float*)d_in[5];
    float* out = (float*)d_out;

    fused_kernel<<<NBLK, 128>>>(pred, target, mask, grad_x, grad_y, offset, out);
}

// round 15
// speedup vs baseline: 1.0655x; 1.0655x over previous
#include <cuda_runtime.h>
#include <math.h>

#define N_BOX 256
#define M_PTS 512
#define KHALF 128                 // k-pairs per block (256 m-points)
#define NBLK  (N_BOX * 2 * 2)     // 1024: boxes x 2 j-halves x 2 k-halves

// c2 = log2(e) / (2 * THETA2^2), THETA2 = 400
#define C2  (1.44269504088896340736f / 320000.0f)
#define L2E 1.44269504088896340736f

__device__ float g_partials[NBLK];
__device__ unsigned int g_count = 0u;   // reset by last block each run

typedef unsigned long long ull;

__device__ __forceinline__ ull pk(float lo, float hi) {
    ull r; asm("mov.b64 %0, {%1, %2};" : "=l"(r) : "f"(lo), "f"(hi)); return r;
}
__device__ __forceinline__ void upk(float& lo, float& hi, ull v) {
    asm("mov.b64 {%0, %1}, %2;" : "=f"(lo), "=f"(hi) : "l"(v));
}
__device__ __forceinline__ float ex2s(float x) {
    float y; asm("ex2.approx.f32 %0, %1;" : "=f"(y) : "f"(x)); return y;
}

struct PrepOut {
    float mx, my, P, u, v;   // k-side
    float Gx, Gy, gx, gy;    // j-side
};

// ---------------------------------------------------------------------------
// Fully fused kernel (R9 frame). Block = (box i, j-half, k-half); 128 thr.
// Phase 1: inline prep (2 k-side m-points -> one 48B smem slot, 2 j-side
// m-points -> registers). Phase 2: 2 j's/thread over 128 k-pairs, f32x2
// packed; asm body INTERLEAVES the two j-chains: both t-chains, then a
// 4-deep ex2 burst, then both accumulations (fills FMA->MUFU latency).
// Phase 3: deterministic block + grid reduction via completion counter.
// ---------------------------------------------------------------------------
__global__ void __launch_bounds__(128, 7) fused_kernel(
    const float* __restrict__ pred,
    const float* __restrict__ target,
    const float* __restrict__ mask,
    const float* __restrict__ grad_x,
    const float* __restrict__ grad_y,
    const float* __restrict__ offset,
    float* __restrict__ out)
{
    __shared__ __align__(16) ull sK[KHALF * 6];  // 48B per k-pair, interleaved
    __shared__ float sWarp[4];
    __shared__ int   sLast;

    const int b   = blockIdx.x;
    const int i   = b >> 2;
    const int jc  = (b >> 1) & 1;
    const int kc  = b & 1;
    const int tid = threadIdx.x;

    // ---- per-box scalars (uniform within block; broadcast loads) ----
    const float off0 = offset[2 * i], off1 = offset[2 * i + 1];
    const float px = pred[5 * i]     - off0;
    const float py = pred[5 * i + 1] - off1;
    const float pw = pred[5 * i + 2];
    const float ph = pred[5 * i + 3];
    const float pa = pred[5 * i + 4];
    const float gxc = target[5 * i]     - off0;
    const float gyc = target[5 * i + 1] - off1;
    const float gw  = target[5 * i + 2];
    const float gh  = target[5 * i + 3];
    const float ga  = target[5 * i + 4];

    float cga, sga;  sincosf(ga, &sga, &cga);
    float cpa, spa;  sincosf(pa, &spa, &cpa);
    const float inv_gw = 1.0f / gw;
    const float inv_gh = 1.0f / gh;

    // ---- inline prep for one m-point ----
    auto prep = [&](int m) -> PrepOut {
        const int idx = i * M_PTS + m;
        const float2 mm = ((const float2*)mask)[idx];
        const float mx = mm.x, my = mm.y;

        const float dx = mx - gxc, dy = my - gyc;
        const float r2  = dx * dx + dy * dy;
        const float rin = rsqrtf(fmaxf(r2, 1e-30f));
        const float d   = r2 * rin;
        float arg = -dx * rin;                       // cos(acosv)
        arg = fminf(1.0f, fmaxf(-1.0f, arg));
        const float st = fabsf(dy) * rin;            // sin(acosv)
        const bool  spos = (gyc >= my);              // beta = ga + s*acosv
        const float s = spos ? 1.0f : -1.0f;

        const float cb = cga * arg - s * (sga * st); // cos(beta)
        const float sb = sga * arg + s * (cga * st); // sin(beta)

        const float d_w = fabsf(d * cb);
        const float d_h = fabsf(d * sb);

        const float e1 = ex2s(L2E * 15.0f * (d_w - gw) * inv_gw);
        const float e2 = ex2s(L2E * 15.0f * (d_h - gh) * inv_gh);
        const float a1 = 1.0f / ((1.0f + e1) * (1.0f + e2));

        const float dwp = pw * d_w * inv_gw;
        const float dhp = ph * d_h * inv_gh;
        const float wx =  dwp * cpa, wy = dwp * spa;
        const float hx = -dhp * spa, hy = dhp * cpa;

        bool q2, q3, q4;
        if (spos) {
            q2 = (ga <= 0.0f) && (arg >= cga);
            q3 = false;
            q4 = (arg < sga) && ((ga <= 0.0f) || (arg >= -cga));
        } else {
            q2 = (arg > -sga) && ((ga <= 0.0f) || (arg <= cga));
            q3 = (arg <= -sga) && ((ga >= 0.0f) || (arg > -cga));
            q4 = false;
        }

        float gpx, gpy;
        if (q2)      { gpx =  wx - hx;  gpy =  wy - hy; }
        else if (q3) { gpx =  wx + hx;  gpy =  wy + hy; }
        else if (q4) { gpx = -wx + hx;  gpy = -wy + hy; }
        else         { gpx = -wx - hx;  gpy = -wy - hy; }

        const float gxv = grad_x[idx];
        const float gyv = grad_y[idx];

        PrepOut o;
        o.mx = mx; o.my = my;
        o.P  = C2 * (mx * mx + my * my);
        o.u  = a1 * gxv;
        o.v  = a1 * gyv;
        o.Gx = px + gpx; o.Gy = py + gpy;
        o.gx = gxv; o.gy = gyv;
        return o;
    };

    // ---- phase 1a: k-side (pair slot tid, m = kc*256 + 2tid, +1) ----
    {
        const int m0 = kc * 256 + 2 * tid;
        const PrepOut k0 = prep(m0);
        const PrepOut k1 = prep(m0 + 1);
        ull* dst = &sK[tid * 6];
        ((float4*)dst)[0] = make_float4(k0.mx, k1.mx, k0.my, k1.my);
        ((float4*)dst)[1] = make_float4(k0.P,  k1.P,  k0.u,  k1.u);
        ((float2*)dst)[4] = make_float2(k0.v,  k1.v);
    }

    // ---- phase 1b: j-side (own j's: jc*256 + tid, +128) ----
    const PrepOut J0 = prep(jc * 256 + tid);
    const PrepOut J1 = prep(jc * 256 + tid + 128);
    __syncthreads();

    const ull na0 = pk(-2.0f * C2 * J0.Gx, -2.0f * C2 * J0.Gx);
    const ull nb0 = pk(-2.0f * C2 * J0.Gy, -2.0f * C2 * J0.Gy);
    const ull na1 = pk(-2.0f * C2 * J1.Gx, -2.0f * C2 * J1.Gx);
    const ull nb1 = pk(-2.0f * C2 * J1.Gy, -2.0f * C2 * J1.Gy);
    const float twoQ0 = ex2s(C2 * (J0.Gx * J0.Gx + J0.Gy * J0.Gy));
    const float twoQ1 = ex2s(C2 * (J1.Gx * J1.Gx + J1.Gy * J1.Gy));

    // ---- phase 2: core loop (interleaved j-chains) ----
    ull A0 = 0, B0 = 0, A1 = 0, B1 = 0;
    const ull* p = sK;

#pragma unroll 4
    for (int k2 = 0; k2 < KHALF; ++k2, p += 6) {
        ulonglong2 xy = *(const ulonglong2*)(p);      // (mx0,mx1),(my0,my1)
        ulonglong2 pu = *(const ulonglong2*)(p + 2);  // (P0,P1),(u0,u1)
        ull        v2 = p[4];                         // (v0,v1)

        asm volatile(
            "{\n\t"
            ".reg .f32 t0l, t0h, t1l, t1h, e0l, e0h, e1l, e1h;\n\t"
            ".reg .b64 t0, t1, e0, e1;\n\t"
            // both t-chains first (independent FMA work)
            "fma.rn.f32x2 t0, %4, %8, %10;\n\t"
            "fma.rn.f32x2 t1, %6, %8, %10;\n\t"
            "fma.rn.f32x2 t0, %5, %9, t0;\n\t"
            "fma.rn.f32x2 t1, %7, %9, t1;\n\t"
            "mov.b64 {t0l, t0h}, t0;\n\t"
            "mov.b64 {t1l, t1h}, t1;\n\t"
            // 4-deep MUFU burst
            "ex2.approx.f32 e0l, t0l;\n\t"
            "ex2.approx.f32 e0h, t0h;\n\t"
            "ex2.approx.f32 e1l, t1l;\n\t"
            "ex2.approx.f32 e1h, t1h;\n\t"
            "mov.b64 e0, {e0l, e0h};\n\t"
            "mov.b64 e1, {e1l, e1h};\n\t"
            // both accumulations
            "fma.rn.f32x2 %0, e0, %11, %0;\n\t"
            "fma.rn.f32x2 %1, e0, %12, %1;\n\t"
            "fma.rn.f32x2 %2, e1, %11, %2;\n\t"
            "fma.rn.f32x2 %3, e1, %12, %3;\n\t"
            "}"
            : "+l"(A0), "+l"(B0), "+l"(A1), "+l"(B1)
            : "l"(na0), "l"(nb0), "l"(na1), "l"(nb1),
              "l"(xy.x), "l"(xy.y), "l"(pu.x), "l"(pu.y), "l"(v2));
    }

    float al, ah, bl, bh;
    upk(al, ah, A0); upk(bl, bh, B0);
    float partial = (J0.gx * (al + ah) + J0.gy * (bl + bh)) * twoQ0;
    upk(al, ah, A1); upk(bl, bh, B1);
    partial += (J1.gx * (al + ah) + J1.gy * (bl + bh)) * twoQ1;

    // ---- phase 3: deterministic block reduction (4 warps) ----
#pragma unroll
    for (int o = 16; o > 0; o >>= 1)
        partial += __shfl_down_sync(0xffffffffu, partial, o);
    if ((tid & 31) == 0) sWarp[tid >> 5] = partial;
    __syncthreads();

    if (tid == 0) {
        g_partials[b] = sWarp[0] + sWarp[1] + sWarp[2] + sWarp[3];
        __threadfence();
        unsigned int old = atomicAdd(&g_count, 1u);
        sLast = (old == NBLK - 1) ? 1 : 0;
    }
    __syncthreads();

    // last block: fixed-order final reduction (deterministic regardless of
    // which block executes it), then reset the counter for the next replay.
    if (sLast) {
        float s = 0.0f;
#pragma unroll
        for (int r = 0; r < NBLK / 128; ++r)
            s += __ldcg(&g_partials[tid + r * 128]);
#pragma unroll
        for (int o = 16; o > 0; o >>= 1)
            s += __shfl_down_sync(0xffffffffu, s, o);
        if ((tid & 31) == 0) sWarp[tid >> 5] = s;
        __syncthreads();
        if (tid == 0) {
            float v = sWarp[0] + sWarp[1] + sWarp[2] + sWarp[3];
            const double scale = 1.0 / ((double)N_BOX * (double)M_PTS * (double)M_PTS *
                                        2.0 * 3.14159265358979323846 * 400.0);
            *out = (float)((double)v * scale);
            g_count = 0u;   // ready for next graph replay
        }
    }
}

// ---------------------------------------------------------------------------
extern "C" void kernel_launch(void* const* d_in, const int* in_sizes, int n_in,
                              void* d_out, int out_size)
{
    const float* pred    = (const float*)d_in[0];
    const float* target  = (const float*)d_in[1];
    const float* mask    = (const float*)d_in[2];
    const float* grad_x  = (const float*)d_in[3];
    const float* grad_y  = (const float*)d_in[4];
    const float* offset  = (const float*)d_in[5];
    float* out = (float*)d_out;

    fused_kernel<<<NBLK, 128>>>(pred, target, mask, grad_x, grad_y, offset, out);
}

// round 16
// speedup vs baseline: 1.0692x; 1.0035x over previous
#include <cuda_runtime.h>
#include <math.h>

#define N_BOX 256
#define M_PTS 512
#define KHALF 128                 // k-pairs per block (256 m-points)
#define NBLK  (N_BOX * 2 * 2)     // 1024: boxes x 2 j-halves x 2 k-halves

// c2 = log2(e) / (2 * THETA2^2), THETA2 = 400
#define C2  (1.44269504088896340736f / 320000.0f)
#define L2E 1.44269504088896340736f

__device__ float g_partials[NBLK];
__device__ unsigned int g_count = 0u;   // reset by last block each run

typedef unsigned long long ull;

__device__ __forceinline__ ull pk(float lo, float hi) {
    ull r; asm("mov.b64 %0, {%1, %2};" : "=l"(r) : "f"(lo), "f"(hi)); return r;
}
__device__ __forceinline__ void upk(float& lo, float& hi, ull v) {
    asm("mov.b64 {%0, %1}, %2;" : "=f"(lo), "=f"(hi) : "l"(v));
}
__device__ __forceinline__ float ex2s(float x) {
    float y; asm("ex2.approx.f32 %0, %1;" : "=f"(y) : "f"(x)); return y;
}

struct PrepOut {
    float mx, my, P, u, v;   // k-side
    float Gx, Gy, gx, gy;    // j-side
};

// ---------------------------------------------------------------------------
// Fully fused kernel (R15 frame). Block = (box i, j-half, k-half); 128 thr.
// Phase 1: inline prep (2 k-side m-points -> one 48B smem slot, 2 j-side
// m-points -> registers). Phase 2: 2 j's/thread over 128 k-pairs, f32x2
// packed, interleaved j-chains with a 4-deep ex2 burst; smem operands are
// SOFTWARE-PIPELINED one iteration ahead so the opaque asm body never waits
// on an LDS arm. Phase 3: deterministic block + grid reduction.
// ---------------------------------------------------------------------------
__global__ void __launch_bounds__(128, 7) fused_kernel(
    const float* __restrict__ pred,
    const float* __restrict__ target,
    const float* __restrict__ mask,
    const float* __restrict__ grad_x,
    const float* __restrict__ grad_y,
    const float* __restrict__ offset,
    float* __restrict__ out)
{
    __shared__ __align__(16) ull sK[KHALF * 6];  // 48B per k-pair, interleaved
    __shared__ float sWarp[4];
    __shared__ int   sLast;

    const int b   = blockIdx.x;
    const int i   = b >> 2;
    const int jc  = (b >> 1) & 1;
    const int kc  = b & 1;
    const int tid = threadIdx.x;

    // ---- per-box scalars (uniform within block; broadcast loads) ----
    const float off0 = offset[2 * i], off1 = offset[2 * i + 1];
    const float px = pred[5 * i]     - off0;
    const float py = pred[5 * i + 1] - off1;
    const float pw = pred[5 * i + 2];
    const float ph = pred[5 * i + 3];
    const float pa = pred[5 * i + 4];
    const float gxc = target[5 * i]     - off0;
    const float gyc = target[5 * i + 1] - off1;
    const float gw  = target[5 * i + 2];
    const float gh  = target[5 * i + 3];
    const float ga  = target[5 * i + 4];

    float cga, sga;  sincosf(ga, &sga, &cga);
    float cpa, spa;  sincosf(pa, &spa, &cpa);
    const float inv_gw = 1.0f / gw;
    const float inv_gh = 1.0f / gh;

    // ---- inline prep for one m-point ----
    auto prep = [&](int m) -> PrepOut {
        const int idx = i * M_PTS + m;
        const float2 mm = ((const float2*)mask)[idx];
        const float mx = mm.x, my = mm.y;

        const float dx = mx - gxc, dy = my - gyc;
        const float r2  = dx * dx + dy * dy;
        const float rin = rsqrtf(fmaxf(r2, 1e-30f));
        const float d   = r2 * rin;
        float arg = -dx * rin;                       // cos(acosv)
        arg = fminf(1.0f, fmaxf(-1.0f, arg));
        const float st = fabsf(dy) * rin;            // sin(acosv)
        const bool  spos = (gyc >= my);              // beta = ga + s*acosv
        const float s = spos ? 1.0f : -1.0f;

        const float cb = cga * arg - s * (sga * st); // cos(beta)
        const float sb = sga * arg + s * (cga * st); // sin(beta)

        const float d_w = fabsf(d * cb);
        const float d_h = fabsf(d * sb);

        const float e1 = ex2s(L2E * 15.0f * (d_w - gw) * inv_gw);
        const float e2 = ex2s(L2E * 15.0f * (d_h - gh) * inv_gh);
        const float a1 = 1.0f / ((1.0f + e1) * (1.0f + e2));

        const float dwp = pw * d_w * inv_gw;
        const float dhp = ph * d_h * inv_gh;
        const float wx =  dwp * cpa, wy = dwp * spa;
        const float hx = -dhp * spa, hy = dhp * cpa;

        bool q2, q3, q4;
        if (spos) {
            q2 = (ga <= 0.0f) && (arg >= cga);
            q3 = false;
            q4 = (arg < sga) && ((ga <= 0.0f) || (arg >= -cga));
        } else {
            q2 = (arg > -sga) && ((ga <= 0.0f) || (arg <= cga));
            q3 = (arg <= -sga) && ((ga >= 0.0f) || (arg > -cga));
            q4 = false;
        }

        float gpx, gpy;
        if (q2)      { gpx =  wx - hx;  gpy =  wy - hy; }
        else if (q3) { gpx =  wx + hx;  gpy =  wy + hy; }
        else if (q4) { gpx = -wx + hx;  gpy = -wy + hy; }
        else         { gpx = -wx - hx;  gpy = -wy - hy; }

        const float gxv = grad_x[idx];
        const float gyv = grad_y[idx];

        PrepOut o;
        o.mx = mx; o.my = my;
        o.P  = C2 * (mx * mx + my * my);
        o.u  = a1 * gxv;
        o.v  = a1 * gyv;
        o.Gx = px + gpx; o.Gy = py + gpy;
        o.gx = gxv; o.gy = gyv;
        return o;
    };

    // ---- phase 1a: k-side (pair slot tid, m = kc*256 + 2tid, +1) ----
    {
        const int m0 = kc * 256 + 2 * tid;
        const PrepOut k0 = prep(m0);
        const PrepOut k1 = prep(m0 + 1);
        ull* dst = &sK[tid * 6];
        ((float4*)dst)[0] = make_float4(k0.mx, k1.mx, k0.my, k1.my);
        ((float4*)dst)[1] = make_float4(k0.P,  k1.P,  k0.u,  k1.u);
        ((float2*)dst)[4] = make_float2(k0.v,  k1.v);
    }

    // ---- phase 1b: j-side (own j's: jc*256 + tid, +128) ----
    const PrepOut J0 = prep(jc * 256 + tid);
    const PrepOut J1 = prep(jc * 256 + tid + 128);
    __syncthreads();

    const ull na0 = pk(-2.0f * C2 * J0.Gx, -2.0f * C2 * J0.Gx);
    const ull nb0 = pk(-2.0f * C2 * J0.Gy, -2.0f * C2 * J0.Gy);
    const ull na1 = pk(-2.0f * C2 * J1.Gx, -2.0f * C2 * J1.Gx);
    const ull nb1 = pk(-2.0f * C2 * J1.Gy, -2.0f * C2 * J1.Gy);
    const float twoQ0 = ex2s(C2 * (J0.Gx * J0.Gx + J0.Gy * J0.Gy));
    const float twoQ1 = ex2s(C2 * (J1.Gx * J1.Gx + J1.Gy * J1.Gy));

    // ---- phase 2: core loop, software-pipelined by one iteration ----
    ull A0 = 0, B0 = 0, A1 = 0, B1 = 0;
    const ull* p = sK;

    // prefetch iteration 0
    ulonglong2 xy = *(const ulonglong2*)(p);
    ulonglong2 pu = *(const ulonglong2*)(p + 2);
    ull        v2 = p[4];

#pragma unroll 8
    for (int k2 = 0; k2 < KHALF; ++k2) {
        // current operands (already in registers)
        const ulonglong2 cxy = xy;
        const ulonglong2 cpu = pu;
        const ull        cv2 = v2;

        // prefetch next iteration (except on the last)
        if (k2 + 1 < KHALF) {
            const ull* q = p + 6;
            xy = *(const ulonglong2*)(q);
            pu = *(const ulonglong2*)(q + 2);
            v2 = q[4];
            p = q;
        }

        asm volatile(
            "{\n\t"
            ".reg .f32 t0l, t0h, t1l, t1h, e0l, e0h, e1l, e1h;\n\t"
            ".reg .b64 t0, t1, e0, e1;\n\t"
            // both t-chains first (independent FMA work)
            "fma.rn.f32x2 t0, %4, %8, %10;\n\t"
            "fma.rn.f32x2 t1, %6, %8, %10;\n\t"
            "fma.rn.f32x2 t0, %5, %9, t0;\n\t"
            "fma.rn.f32x2 t1, %7, %9, t1;\n\t"
            "mov.b64 {t0l, t0h}, t0;\n\t"
            "mov.b64 {t1l, t1h}, t1;\n\t"
            // 4-deep MUFU burst
            "ex2.approx.f32 e0l, t0l;\n\t"
            "ex2.approx.f32 e0h, t0h;\n\t"
            "ex2.approx.f32 e1l, t1l;\n\t"
            "ex2.approx.f32 e1h, t1h;\n\t"
            "mov.b64 e0, {e0l, e0h};\n\t"
            "mov.b64 e1, {e1l, e1h};\n\t"
            // both accumulations
            "fma.rn.f32x2 %0, e0, %11, %0;\n\t"
            "fma.rn.f32x2 %1, e0, %12, %1;\n\t"
            "fma.rn.f32x2 %2, e1, %11, %2;\n\t"
            "fma.rn.f32x2 %3, e1, %12, %3;\n\t"
            "}"
            : "+l"(A0), "+l"(B0), "+l"(A1), "+l"(B1)
            : "l"(na0), "l"(nb0), "l"(na1), "l"(nb1),
              "l"(cxy.x), "l"(cxy.y), "l"(cpu.x), "l"(cpu.y), "l"(cv2));
    }

    float al, ah, bl, bh;
    upk(al, ah, A0); upk(bl, bh, B0);
    float partial = (J0.gx * (al + ah) + J0.gy * (bl + bh)) * twoQ0;
    upk(al, ah, A1); upk(bl, bh, B1);
    partial += (J1.gx * (al + ah) + J1.gy * (bl + bh)) * twoQ1;

    // ---- phase 3: deterministic block reduction (4 warps) ----
#pragma unroll
    for (int o = 16; o > 0; o >>= 1)
        partial += __shfl_down_sync(0xffffffffu, partial, o);
    if ((tid & 31) == 0) sWarp[tid >> 5] = partial;
    __syncthreads();

    if (tid == 0) {
        g_partials[b] = sWarp[0] + sWarp[1] + sWarp[2] + sWarp[3];
        __threadfence();
        unsigned int old = atomicAdd(&g_count, 1u);
        sLast = (old == NBLK - 1) ? 1 : 0;
    }
    __syncthreads();

    // last block: fixed-order final reduction (deterministic regardless of
    // which block executes it), then reset the counter for the next replay.
    if (sLast) {
        float s = 0.0f;
#pragma unroll
        for (int r = 0; r < NBLK / 128; ++r)
            s += __ldcg(&g_partials[tid + r * 128]);
#pragma unroll
        for (int o = 16; o > 0; o >>= 1)
            s += __shfl_down_sync(0xffffffffu, s, o);
        if ((tid & 31) == 0) sWarp[tid >> 5] = s;
        __syncthreads();
        if (tid == 0) {
            float v = sWarp[0] + sWarp[1] + sWarp[2] + sWarp[3];
            const double scale = 1.0 / ((double)N_BOX * (double)M_PTS * (double)M_PTS *
                                        2.0 * 3.14159265358979323846 * 400.0);
            *out = (float)((double)v * scale);
            g_count = 0u;   // ready for next graph replay
        }
    }
}

// ---------------------------------------------------------------------------
extern "C" void kernel_launch(void* const* d_in, const int* in_sizes, int n_in,
                              void* d_out, int out_size)
{
    const float* pred    = (const float*)d_in[0];
    const float* target  = (const float*)d_in[1];
    const float* mask    = (const float*)d_in[2];
    const float* grad_x  = (const float*)d_in[3];
    const float* grad_y  = (const float*)d_in[4];
    const float* offset  = (const float*)d_in[5];
    float* out = (float*)d_out;

    fused_kernel<<<NBLK, 128>>>(pred, target, mask, grad_x, grad_y, offset, out);
}

// round 17
// speedup vs baseline: 1.5209x; 1.4224x over previous
#include <cuda_runtime.h>
#include <math.h>

#define N_BOX 256
#define M_PTS 512
#define KH    256                 // k-points per block (k-half)
#define NBLK  (N_BOX * 4 * 2)     // 2048: boxes x 4 j-quarters x 2 k-halves

// c2 = log2(e) / (2 * THETA2^2), THETA2 = 400
#define C2  (1.44269504088896340736f / 320000.0f)
#define L2E 1.44269504088896340736f
#define ACUT 16.0f                // sigmoid-arg cutoff: a1 < 1.1e-7 beyond

__device__ float g_partials[NBLK];
__device__ unsigned int g_count = 0u;   // reset by last block each run

__device__ __forceinline__ float ex2s(float x) {
    float y; asm("ex2.approx.f32 %0, %1;" : "=f"(y) : "f"(x)); return y;
}

struct KOut {
    float mx, my, P, u, v;   // k-side payload
    bool  keep;              // survivor flag (a1 above cutoff)
};
struct JOut {
    float Gx, Gy, gx, gy;    // j-side payload
};

// ---------------------------------------------------------------------------
// Sparse fused kernel. Block = (box i, j-quarter, k-half); 128 threads.
// Phase 1: inline prep. Each thread preps 2 k-points (k = kh*256+2t, +1)
//   with survivor flags, and 1 j-point (j = jq*128 + t).
// Phase 2: deterministic compaction (warp-scan prefix, k-order preserved)
//   of survivors into smem. ~28% of k-points survive the a1 window.
// Phase 3: each thread loops its single j over cnt survivors (scalar core:
//   2 FFMA + 1 ex2 + 2 FFMA; all smem loads are broadcasts).
// Phase 4: deterministic block + grid reduction via completion counter.
// ---------------------------------------------------------------------------
__global__ void __launch_bounds__(128, 8) fused_kernel(
    const float* __restrict__ pred,
    const float* __restrict__ target,
    const float* __restrict__ mask,
    const float* __restrict__ grad_x,
    const float* __restrict__ grad_y,
    const float* __restrict__ offset,
    float* __restrict__ out)
{
    __shared__ __align__(16) float4 sC[KH];  // mx, my, P, u (compacted)
    __shared__ float sV[KH];                 // v (compacted)
    __shared__ int   sWt[4];
    __shared__ float sWarp[4];
    __shared__ int   sLast;

    const int b   = blockIdx.x;
    const int i   = b >> 3;
    const int jq  = (b >> 1) & 3;
    const int kh  = b & 1;
    const int tid = threadIdx.x;
    const int lane = tid & 31;
    const int wid  = tid >> 5;

    // ---- per-box scalars (uniform within block; broadcast loads) ----
    const float off0 = offset[2 * i], off1 = offset[2 * i + 1];
    const float px = pred[5 * i]     - off0;
    const float py = pred[5 * i + 1] - off1;
    const float pw = pred[5 * i + 2];
    const float ph = pred[5 * i + 3];
    const float pa = pred[5 * i + 4];
    const float gxc = target[5 * i]     - off0;
    const float gyc = target[5 * i + 1] - off1;
    const float gw  = target[5 * i + 2];
    const float gh  = target[5 * i + 3];
    const float ga  = target[5 * i + 4];

    float cga, sga;  sincosf(ga, &sga, &cga);
    float cpa, spa;  sincosf(pa, &spa, &cpa);
    const float inv_gw = 1.0f / gw;
    const float inv_gh = 1.0f / gh;

    // ---- shared geometric sub-prep ----
    auto geo = [&](int m, float& d_w, float& d_h, float& arg_, float& st_,
                   float& s_, float& mx_, float& my_) {
        const int idx = i * M_PTS + m;
        const float2 mm = ((const float2*)mask)[idx];
        mx_ = mm.x; my_ = mm.y;
        const float dx = mm.x - gxc, dy = mm.y - gyc;
        const float r2  = dx * dx + dy * dy;
        const float rin = rsqrtf(fmaxf(r2, 1e-30f));
        const float d   = r2 * rin;
        float arg = -dx * rin;
        arg = fminf(1.0f, fmaxf(-1.0f, arg));
        const float st = fabsf(dy) * rin;
        const float s = (gyc >= mm.y) ? 1.0f : -1.0f;
        const float cb = cga * arg - s * (sga * st);
        const float sb = sga * arg + s * (cga * st);
        d_w = fabsf(d * cb);
        d_h = fabsf(d * sb);
        arg_ = arg; st_ = st; s_ = s;
    };

    // ---- k-side prep with survivor flag ----
    auto prepK = [&](int m) -> KOut {
        const int idx = i * M_PTS + m;
        float d_w, d_h, arg, st, s, mx, my;
        geo(m, d_w, d_h, arg, st, s, mx, my);

        const float a1arg1 = 15.0f * (d_w - gw) * inv_gw;
        const float a1arg2 = 15.0f * (d_h - gh) * inv_gh;

        KOut o;
        o.keep = (a1arg1 < ACUT) && (a1arg2 < ACUT);
        const float e1 = ex2s(L2E * a1arg1);
        const float e2 = ex2s(L2E * a1arg2);
        const float a1 = 1.0f / ((1.0f + e1) * (1.0f + e2));
        o.mx = mx; o.my = my;
        o.P  = C2 * (mx * mx + my * my);
        o.u  = a1 * grad_x[idx];
        o.v  = a1 * grad_y[idx];
        return o;
    };

    // ---- j-side prep ----
    auto prepJ = [&](int m) -> JOut {
        const int idx = i * M_PTS + m;
        float d_w, d_h, arg, st, s, mx, my;
        geo(m, d_w, d_h, arg, st, s, mx, my);

        const float dwp = pw * d_w * inv_gw;
        const float dhp = ph * d_h * inv_gh;
        const float wx =  dwp * cpa, wy = dwp * spa;
        const float hx = -dhp * spa, hy = dhp * cpa;

        const bool spos = (s > 0.0f);
        bool q2, q3, q4;
        if (spos) {
            q2 = (ga <= 0.0f) && (arg >= cga);
            q3 = false;
            q4 = (arg < sga) && ((ga <= 0.0f) || (arg >= -cga));
        } else {
            q2 = (arg > -sga) && ((ga <= 0.0f) || (arg <= cga));
            q3 = (arg <= -sga) && ((ga >= 0.0f) || (arg > -cga));
            q4 = false;
        }

        float gpx, gpy;
        if (q2)      { gpx =  wx - hx;  gpy =  wy - hy; }
        else if (q3) { gpx =  wx + hx;  gpy =  wy + hy; }
        else if (q4) { gpx = -wx + hx;  gpy = -wy + hy; }
        else         { gpx = -wx - hx;  gpy = -wy - hy; }

        JOut o;
        o.Gx = px + gpx; o.Gy = py + gpy;
        o.gx = grad_x[idx]; o.gy = grad_y[idx];
        return o;
    };

    // ---- phase 1: prep 2 k-points + 1 j-point per thread ----
    const int m0 = kh * KH + 2 * tid;
    const KOut k0 = prepK(m0);
    const KOut k1 = prepK(m0 + 1);
    const JOut J  = prepJ(jq * 128 + tid);

    // ---- phase 2: deterministic compaction (k-order preserved) ----
    const int fl0 = k0.keep ? 1 : 0;
    const int fl1 = k1.keep ? 1 : 0;
    const int local = fl0 + fl1;
    int pre = local;
#pragma unroll
    for (int o = 1; o < 32; o <<= 1) {
        const int n = __shfl_up_sync(0xffffffffu, pre, o);
        if (lane >= o) pre += n;
    }
    if (lane == 31) sWt[wid] = pre;
    __syncthreads();
    int base = 0;
#pragma unroll
    for (int w = 0; w < 4; ++w) base += (w < wid) ? sWt[w] : 0;
    const int cnt = sWt[0] + sWt[1] + sWt[2] + sWt[3];
    int slot = base + pre - local;
    if (fl0) {
        sC[slot] = make_float4(k0.mx, k0.my, k0.P, k0.u);
        sV[slot] = k0.v;
        slot++;
    }
    if (fl1) {
        sC[slot] = make_float4(k1.mx, k1.my, k1.P, k1.u);
        sV[slot] = k1.v;
    }
    __syncthreads();

    // ---- phase 3: scalar core over survivors (uniform loop; broadcasts) ----
    const float na = -2.0f * C2 * J.Gx;
    const float nb = -2.0f * C2 * J.Gy;
    const float twoQ = ex2s(C2 * (J.Gx * J.Gx + J.Gy * J.Gy));

    float A = 0.0f, B = 0.0f;
#pragma unroll 4
    for (int s = 0; s < cnt; ++s) {
        const float4 kd = sC[s];
        const float  vv = sV[s];
        float t = fmaf(na, kd.x, kd.z);
        t = fmaf(nb, kd.y, t);
        const float e = ex2s(t);
        A = fmaf(e, kd.w, A);
        B = fmaf(e, vv, B);
    }
    float partial = (J.gx * A + J.gy * B) * twoQ;

    // ---- phase 4: deterministic block reduction (4 warps) ----
#pragma unroll
    for (int o = 16; o > 0; o >>= 1)
        partial += __shfl_down_sync(0xffffffffu, partial, o);
    if (lane == 0) sWarp[wid] = partial;
    __syncthreads();

    if (tid == 0) {
        g_partials[b] = sWarp[0] + sWarp[1] + sWarp[2] + sWarp[3];
        __threadfence();
        unsigned int old = atomicAdd(&g_count, 1u);
        sLast = (old == NBLK - 1) ? 1 : 0;
    }
    __syncthreads();

    // last block: fixed-order final reduction (deterministic regardless of
    // which block executes it), then reset the counter for the next replay.
    if (sLast) {
        float s = 0.0f;
#pragma unroll
        for (int r = 0; r < NBLK / 128; ++r)
            s += __ldcg(&g_partials[tid + r * 128]);
#pragma unroll
        for (int o = 16; o > 0; o >>= 1)
            s += __shfl_down_sync(0xffffffffu, s, o);
        if (lane == 0) sWarp[wid] = s;
        __syncthreads();
        if (tid == 0) {
            float v = sWarp[0] + sWarp[1] + sWarp[2] + sWarp[3];
            const double scale = 1.0 / ((double)N_BOX * (double)M_PTS * (double)M_PTS *
                                        2.0 * 3.14159265358979323846 * 400.0);
            *out = (float)((double)v * scale);
            g_count = 0u;   // ready for next graph replay
        }
    }
}

// ---------------------------------------------------------------------------
extern "C" void kernel_launch(void* const* d_in, const int* in_sizes, int n_in,
                              void* d_out, int out_size)
{
    const float* pred    = (const float*)d_in[0];
    const float* target  = (const float*)d_in[1];
    const float* mask    = (const float*)d_in[2];
    const float* grad_x  = (const float*)d_in[3];
    const float* grad_y  = (const float*)d_in[4];
    const float* offset  = (const float*)d_in[5];
    float* out = (float*)d_out;

    fused_kernel<<<NBLK, 128>>>(pred, target, mask, grad_x, grad_y, offset, out);
}